// round 17
// baseline (speedup 1.0000x reference)
#include <cuda_runtime.h>
#include <cuda_fp16.h>
#include <cstdint>
#include <math.h>

// ---------------- problem constants ----------------
#define B_ 16
#define L_ 96
#define N_ 512
#define D_ 512
#define H_ 8
#define E_ 64
#define DFF_ 2048
#define T_ 516
#define PRED_ 96
#define NMARK_ 4
#define LAYERS_ 2
#define BT_ (B_ * T_)     // 8256
#define SCALE_ 0.125f

// ---------------- scratch ----------------
__device__ float g_mean[B_ * N_];
__device__ float g_std[B_ * N_];
__device__ float g_guide[B_ * N_ * N_];
__device__ float g_bqkv[LAYERS_ * 3 * D_];
__device__ float g_proj[BT_ * PRED_];
__device__ __half g_tok[B_ * T_ * L_];
__device__ __half g_nt[B_ * N_ * L_];
__device__ __half g_x[BT_ * D_];
__device__ __half g_tmp[BT_ * D_];
__device__ __half g_ctx[BT_ * D_];
__device__ __half g_qkv[(long long)BT_ * 3 * D_];
__device__ __half g_ffn[(long long)BT_ * DFF_];
__device__ __half g_wqkvt[(long long)LAYERS_ * 3 * D_ * D_];
__device__ __half g_wot[LAYERS_ * D_ * D_];
__device__ __half g_w1t[(long long)LAYERS_ * D_ * DFF_];
__device__ __half g_w2t[(long long)LAYERS_ * DFF_ * D_];
__device__ __half g_embt[D_ * L_];
__device__ __half g_projt[PRED_ * D_];

// ---------------- helpers ----------------
__device__ __forceinline__ void mma16(float* c, const uint32_t* a, uint32_t b0, uint32_t b1) {
    asm volatile(
        "mma.sync.aligned.m16n8k16.row.col.f32.f16.f16.f32 "
        "{%0,%1,%2,%3}, {%4,%5,%6,%7}, {%8,%9}, {%0,%1,%2,%3};"
        : "+f"(c[0]), "+f"(c[1]), "+f"(c[2]), "+f"(c[3])
        : "r"(a[0]), "r"(a[1]), "r"(a[2]), "r"(a[3]), "r"(b0), "r"(b1));
}
__device__ __forceinline__ void ldsm4(uint32_t* r, uint32_t addr) {
    asm volatile("ldmatrix.sync.aligned.m8n8.x4.shared.b16 {%0,%1,%2,%3}, [%4];"
        : "=r"(r[0]), "=r"(r[1]), "=r"(r[2]), "=r"(r[3]) : "r"(addr));
}
__device__ __forceinline__ void ldsm4t(uint32_t* r, uint32_t addr) {
    asm volatile("ldmatrix.sync.aligned.m8n8.x4.trans.shared.b16 {%0,%1,%2,%3}, [%4];"
        : "=r"(r[0]), "=r"(r[1]), "=r"(r[2]), "=r"(r[3]) : "r"(addr));
}
__device__ __forceinline__ uint32_t h2pack(float a, float b) {
    __half2 h = __floats2half2_rn(a, b);
    return *reinterpret_cast<uint32_t*>(&h);
}
__device__ __forceinline__ float geluf(float x) {
    return 0.5f * x * (1.0f + erff(x * 0.70710678118654752f));
}
__device__ __forceinline__ uint32_t smem_u32(const void* p) {
    uint32_t a;
    asm("{ .reg .u64 t; cvta.to.shared.u64 t, %1; cvt.u32.u64 %0, t; }" : "=r"(a) : "l"(p));
    return a;
}
__device__ __forceinline__ void cp16_full(uint32_t dst, const void* src) {
    asm volatile("cp.async.cg.shared.global [%0], [%1], 16;" :: "r"(dst), "l"(src) : "memory");
}
__device__ __forceinline__ void cp16_pred(uint32_t dst, const void* src, int nbytes) {
    asm volatile("cp.async.cg.shared.global [%0], [%1], 16, %2;" :: "r"(dst), "l"(src), "r"(nbytes) : "memory");
}
#define CP_COMMIT() asm volatile("cp.async.commit_group;" ::: "memory")
template <int Nw>
__device__ __forceinline__ void cp_wait() {
    asm volatile("cp.async.wait_group %0;" :: "n"(Nw) : "memory");
}

// ---------------- fp16 tensor-core GEMM: C[M,N] = A[M,K] @ B[N,K]^T (+epi) ----------------
// EPI: 0 none, 1 +bias, 2 +bias+gelu, 3 +bias+residual, 4 sigmoid (no bias).
#define SSH 72   // smem row stride in halfs (144B): ldmatrix conflict-free

template <int EPI, typename OT>
__global__ void __launch_bounds__(256, 2)
mmak(const __half* __restrict__ A, const __half* __restrict__ Bm,
     const float* __restrict__ bias, const __half* __restrict__ Res,
     OT* __restrict__ C,
     int M, int Nn, int K, int lda, int ldb, int ldc, int nbH,
     long long sAb, long long sAh, long long sBb, long long sBh,
     long long sCb, long long sCh) {
    constexpr int BNt = 128;
    constexpr int NI = 4;
    constexpr int NP = 2;
    constexpr int AE = 128 * SSH;
    constexpr int STG = 2 * AE;

    extern __shared__ char smem_raw[];
    const uint32_t sbase = smem_u32(smem_raw);

    int tid = threadIdx.x;
    int z = blockIdx.z, zb = z / nbH, zh = z % nbH;
    A  += zb * sAb + zh * sAh;
    Bm += zb * sBb + zh * sBh;
    C  += zb * sCb + zh * sCh;
    int m0 = blockIdx.y * 128, n0 = blockIdx.x * BNt;

    int lane = tid & 31, wid = tid >> 5;
    int wm = (wid & 1) * 64;
    int wn = (wid >> 1) * 32;
    int grp = lane >> 2, tig = lane & 3;
    int ls = lane >> 3, r8 = lane & 7;

    uint32_t offA[4];
#pragma unroll
    for (int mi = 0; mi < 4; mi++) {
        int row = wm + mi * 16 + (ls & 1) * 8 + r8;
        int col = (ls >> 1) * 8;
        offA[mi] = (uint32_t)(row * SSH + col) * 2u;
    }
    uint32_t offB[NP];
#pragma unroll
    for (int pi = 0; pi < NP; pi++) {
        int row = wn + (2 * pi + (ls >> 1)) * 8 + r8;
        int col = (ls & 1) * 8;
        offB[pi] = (uint32_t)(row * SSH + col) * 2u;
    }

    float acc[4][NI][4];
#pragma unroll
    for (int mi = 0; mi < 4; mi++)
#pragma unroll
        for (int ni = 0; ni < NI; ni++)
#pragma unroll
            for (int r = 0; r < 4; r++) acc[mi][ni][r] = 0.f;

    const int NC = (K + 63) >> 6;
    const bool full = (m0 + 128 <= M) && (n0 + BNt <= Nn) && ((K & 63) == 0);
    const int l_row = tid >> 3, l_c8 = (tid & 7) << 3;

    auto issue = [&](int c, int st) {
        int k0 = c * 64;
        uint32_t abase = sbase + (uint32_t)(st * STG) * 2u;
        uint32_t bbase = abase + (uint32_t)AE * 2u;
        if (full) {
#pragma unroll
            for (int u = 0; u < 4; u++) {
                int row = l_row + u * 32;
                cp16_full(abase + (uint32_t)(row * SSH + l_c8) * 2u,
                          A + (long long)(m0 + row) * lda + k0 + l_c8);
                cp16_full(bbase + (uint32_t)(row * SSH + l_c8) * 2u,
                          Bm + (long long)(n0 + row) * ldb + k0 + l_c8);
            }
        } else {
            int gk = k0 + l_c8;
            int rem = K - gk;
            int nbk = rem >= 8 ? 16 : (rem > 0 ? rem * 2 : 0);
#pragma unroll
            for (int u = 0; u < 4; u++) {
                int row = l_row + u * 32;
                int gm = m0 + row;
                int nb = (gm < M) ? nbk : 0;
                const __half* srcA = (nb > 0) ? (A + (long long)gm * lda + gk) : A;
                cp16_pred(abase + (uint32_t)(row * SSH + l_c8) * 2u, srcA, nb);
                int gn = n0 + row;
                int nb2 = (gn < Nn) ? nbk : 0;
                const __half* srcB = (nb2 > 0) ? (Bm + (long long)gn * ldb + gk) : Bm;
                cp16_pred(bbase + (uint32_t)(row * SSH + l_c8) * 2u, srcB, nb2);
            }
        }
    };

    issue(0, 0);
    CP_COMMIT();

    for (int c = 0; c < NC; c++) {
        cp_wait<0>();
        __syncthreads();
        if (c + 1 < NC) { issue(c + 1, (c + 1) & 1); CP_COMMIT(); }

        uint32_t aB = sbase + (uint32_t)((c & 1) * STG) * 2u;
        uint32_t bB = aB + (uint32_t)AE * 2u;
#pragma unroll
        for (int kk = 0; kk < 4; kk++) {
            uint32_t kof = (uint32_t)kk * 32u;
            uint32_t af[4][4];
#pragma unroll
            for (int mi = 0; mi < 4; mi++) ldsm4(af[mi], aB + offA[mi] + kof);
#pragma unroll
            for (int pi = 0; pi < NP; pi++) {
                uint32_t bb[4];
                ldsm4(bb, bB + offB[pi] + kof);
#pragma unroll
                for (int mi = 0; mi < 4; mi++) {
                    mma16(acc[mi][2 * pi],     af[mi], bb[0], bb[1]);
                    mma16(acc[mi][2 * pi + 1], af[mi], bb[2], bb[3]);
                }
            }
        }
    }

#pragma unroll
    for (int mi = 0; mi < 4; mi++) {
#pragma unroll
        for (int ni = 0; ni < NI; ni++) {
            int col = n0 + wn + ni * 8 + 2 * tig;
            if (col >= Nn) continue;
            float bv0 = 0.f, bv1 = 0.f;
            if (EPI >= 1 && EPI <= 3) { bv0 = bias[col]; bv1 = bias[col + 1]; }
#pragma unroll
            for (int h = 0; h < 2; h++) {
                int gm = m0 + wm + mi * 16 + grp + h * 8;
                if (gm >= M) continue;
                float v0 = acc[mi][ni][h * 2 + 0] + bv0;
                float v1 = acc[mi][ni][h * 2 + 1] + bv1;
                if (EPI == 2) { v0 = geluf(v0); v1 = geluf(v1); }
                if (EPI == 3) {
                    const __half* rp = Res + (long long)gm * ldc + col;
                    v0 += __half2float(rp[0]); v1 += __half2float(rp[1]);
                }
                if (EPI == 4) {
                    v0 = 1.f / (1.f + __expf(-v0));
                    v1 = 1.f / (1.f + __expf(-v1));
                }
                if (sizeof(OT) == 2) {
                    *(uint32_t*)((__half*)C + (long long)gm * ldc + col) = h2pack(v0, v1);
                } else {
                    *(float2*)((float*)C + (long long)gm * ldc + col) = make_float2(v0, v1);
                }
            }
        }
    }
}

// ---------------- fused gated flash attention (fp16 operands) ----------------
#define QSH 136
#define KSH 72
#define FSMEM ((128 * QSH + 2 * 128 * KSH) * 2)

__global__ void __launch_bounds__(256)
flash_k(const __half* __restrict__ qkv, const float* __restrict__ gate,
        __half* __restrict__ ctx) {
    extern __shared__ char sm[];
    __half* Sp = (__half*)sm;
    __half* Sk = Sp + 128 * QSH;
    __half* Sv = Sk + 128 * KSH;

    int qt = blockIdx.x;
    int bh = blockIdx.y;
    int b = bh >> 3, h = bh & 7;
    int i0 = qt * 128;
    int tid = threadIdx.x, lane = tid & 31, w = tid >> 5;
    int grp = lane >> 2, tig = lane & 3;
    int ls = lane >> 3, r8 = lane & 7;

    const __half* qb = qkv + (long long)b * T_ * (3 * D_) + h * E_;
    const __half* kb = qb + D_;
    const __half* vb = qb + 2 * D_;

    const uint32_t spB = smem_u32(Sp);
    const uint32_t skB = smem_u32(Sk);
    const uint32_t svB = smem_u32(Sv);

    uint32_t offPA;
    {
        int row = w * 16 + (ls & 1) * 8 + r8;
        int col = (ls >> 1) * 8;
        offPA = (uint32_t)(row * QSH + col) * 2u;
    }
    uint32_t offKB[8];
#pragma unroll
    for (int pf = 0; pf < 8; pf++) {
        int row = (2 * pf + (ls >> 1)) * 8 + r8;
        int col = (ls & 1) * 8;
        offKB[pf] = (uint32_t)(row * KSH + col) * 2u;
    }
    uint32_t offVB[4];
#pragma unroll
    for (int pe = 0; pe < 4; pe++) {
        int row = (ls & 1) * 8 + r8;
        int col = pe * 16 + (ls >> 1) * 8;
        offVB[pe] = (uint32_t)(row * KSH + col) * 2u;
    }

    for (int e = tid; e < 128 * 8; e += 256) {
        int r = e >> 3, c8 = (e & 7) << 3;
        int gi = i0 + r; if (gi >= T_) gi = T_ - 1;
        *(uint4*)(Sp + r * QSH + c8) = *(const uint4*)(qb + (long long)gi * (3 * D_) + c8);
    }
    __syncthreads();
    uint32_t qf[4][4];
#pragma unroll
    for (int ks = 0; ks < 4; ks++) ldsm4(qf[ks], spB + offPA + (uint32_t)ks * 32u);

    float of[8][4];
#pragma unroll
    for (int nf = 0; nf < 8; nf++)
#pragma unroll
        for (int r = 0; r < 4; r++) of[nf][r] = 0.f;
    float m0 = -1e30f, m1 = -1e30f;
    float s1a = 0.f, s1b = 0.f, s2a = 0.f, s2b = 0.f;

    const float* gb = gate + (long long)b * N_ * N_;
    const int row0 = i0 + w * 16 + grp, row1 = row0 + 8;

    for (int j0 = 0; j0 < T_; j0 += 128) {
        __syncthreads();
        for (int e = tid; e < 128 * 8; e += 256) {
            int r = e >> 3, c8 = (e & 7) << 3;
            int gj = j0 + r; if (gj >= T_) gj = T_ - 1;
            *(uint4*)(Sk + r * KSH + c8) = *(const uint4*)(kb + (long long)gj * (3 * D_) + c8);
            *(uint4*)(Sv + r * KSH + c8) = *(const uint4*)(vb + (long long)gj * (3 * D_) + c8);
        }
        __syncthreads();

        float sf[16][4];
#pragma unroll
        for (int nf = 0; nf < 16; nf++)
#pragma unroll
            for (int r = 0; r < 4; r++) sf[nf][r] = 0.f;
#pragma unroll
        for (int ks = 0; ks < 4; ks++) {
#pragma unroll
            for (int pf = 0; pf < 8; pf++) {
                uint32_t bb[4];
                ldsm4(bb, skB + offKB[pf] + (uint32_t)ks * 32u);
                mma16(sf[2 * pf],     qf[ks], bb[0], bb[1]);
                mma16(sf[2 * pf + 1], qf[ks], bb[2], bb[3]);
            }
        }

        float cm0 = -1e30f, cm1 = -1e30f;
#pragma unroll
        for (int nf = 0; nf < 16; nf++) {
            int j = j0 + nf * 8 + 2 * tig;
            float x0 = sf[nf][0] * SCALE_, x1 = sf[nf][1] * SCALE_;
            float x2 = sf[nf][2] * SCALE_, x3 = sf[nf][3] * SCALE_;
            if (j >= T_)     { x0 = -1e30f; x2 = -1e30f; }
            if (j + 1 >= T_) { x1 = -1e30f; x3 = -1e30f; }
            sf[nf][0] = x0; sf[nf][1] = x1; sf[nf][2] = x2; sf[nf][3] = x3;
            cm0 = fmaxf(cm0, fmaxf(x0, x1));
            cm1 = fmaxf(cm1, fmaxf(x2, x3));
        }
#pragma unroll
        for (int o = 1; o <= 2; o <<= 1) {
            cm0 = fmaxf(cm0, __shfl_xor_sync(0xffffffffu, cm0, o));
            cm1 = fmaxf(cm1, __shfl_xor_sync(0xffffffffu, cm1, o));
        }
        float nm0 = fmaxf(m0, cm0), nm1 = fmaxf(m1, cm1);
        float f0 = __expf(m0 - nm0), f1 = __expf(m1 - nm1);
        m0 = nm0; m1 = nm1;
        s1a *= f0; s2a *= f0; s1b *= f1; s2b *= f1;
#pragma unroll
        for (int nf = 0; nf < 8; nf++) {
            of[nf][0] *= f0; of[nf][1] *= f0;
            of[nf][2] *= f1; of[nf][3] *= f1;
        }

        float ls1a = 0.f, ls1b = 0.f, ls2a = 0.f, ls2b = 0.f;
        int r = w * 16 + grp;
#pragma unroll
        for (int nf = 0; nf < 16; nf++) {
            int j = j0 + nf * 8 + 2 * tig;
            float p0 = __expf(sf[nf][0] - m0), p1 = __expf(sf[nf][1] - m0);
            float p2 = __expf(sf[nf][2] - m1), p3 = __expf(sf[nf][3] - m1);
            float g0 = 0.5f, g1 = 0.5f, g2 = 0.5f, g3 = 0.5f;
            if (j < N_) {
                if (row0 < N_) { float2 gg = *(const float2*)(gb + (long long)row0 * N_ + j); g0 = gg.x; g1 = gg.y; }
                if (row1 < N_) { float2 gg = *(const float2*)(gb + (long long)row1 * N_ + j); g2 = gg.x; g3 = gg.y; }
            }
            ls1a += p0 + p1; ls1b += p2 + p3;
            float q0 = p0 * g0, q1 = p1 * g1, q2 = p2 * g2, q3 = p3 * g3;
            ls2a += q0 + q1; ls2b += q2 + q3;
            *(uint32_t*)(Sp + r * QSH + nf * 8 + 2 * tig) = h2pack(q0, q1);
            *(uint32_t*)(Sp + (r + 8) * QSH + nf * 8 + 2 * tig) = h2pack(q2, q3);
        }
#pragma unroll
        for (int o = 1; o <= 2; o <<= 1) {
            ls1a += __shfl_xor_sync(0xffffffffu, ls1a, o);
            ls1b += __shfl_xor_sync(0xffffffffu, ls1b, o);
            ls2a += __shfl_xor_sync(0xffffffffu, ls2a, o);
            ls2b += __shfl_xor_sync(0xffffffffu, ls2b, o);
        }
        s1a += ls1a; s1b += ls1b; s2a += ls2a; s2b += ls2b;

        __syncwarp();
#pragma unroll
        for (int ks = 0; ks < 8; ks++) {
            uint32_t a[4];
            ldsm4(a, spB + offPA + (uint32_t)ks * 32u);
            uint32_t vof = (uint32_t)(ks * 16 * KSH) * 2u;
#pragma unroll
            for (int pe = 0; pe < 4; pe++) {
                uint32_t bb[4];
                ldsm4t(bb, svB + offVB[pe] + vof);
                mma16(of[2 * pe],     a, bb[0], bb[1]);
                mma16(of[2 * pe + 1], a, bb[2], bb[3]);
            }
        }
    }

    float d0 = 1.f / (s2a + 1e-6f * s1a);
    float d1 = 1.f / (s2b + 1e-6f * s1b);
    __half* cb = ctx + (long long)b * T_ * D_ + h * E_;
#pragma unroll
    for (int nf = 0; nf < 8; nf++) {
        int col = nf * 8 + 2 * tig;
        if (row0 < T_)
            *(uint32_t*)(cb + (long long)row0 * D_ + col) = h2pack(of[nf][0] * d0, of[nf][1] * d0);
        if (row1 < T_)
            *(uint32_t*)(cb + (long long)row1 * D_ + col) = h2pack(of[nf][2] * d1, of[nf][3] * d1);
    }
}

// ---------------- batched tiled transpose: float src -> half dst ----------------
__global__ void transpose_k(const float* __restrict__ S, __half* __restrict__ Dst,
                            int R, int C, int lds, int ldd, int nb2,
                            long long sSb, long long sSh, long long sDb, long long sDh) {
    __shared__ float t[32][33];
    int z = blockIdx.z, zb = z / nb2, zh = z % nb2;
    S += zb * sSb + zh * sSh;
    Dst += zb * sDb + zh * sDh;
    int r0 = blockIdx.y * 32, c0 = blockIdx.x * 32;
    int c = c0 + threadIdx.x;
#pragma unroll
    for (int i = 0; i < 32; i += 8) {
        int r = r0 + threadIdx.y + i;
        if (r < R && c < C) t[threadIdx.y + i][threadIdx.x] = S[(long long)r * lds + c];
    }
    __syncthreads();
    int cc2 = r0 + threadIdx.x;
#pragma unroll
    for (int i = 0; i < 32; i += 8) {
        int rr2 = c0 + threadIdx.y + i;
        if (rr2 < C && cc2 < R) Dst[(long long)rr2 * ldd + cc2] = __float2half(t[threadIdx.x][threadIdx.y + i]);
    }
}

// merged transpose for wq/wk/wv/wo (all [LAYERS,512,512])
__global__ void transpose4_k(const float* __restrict__ wq, const float* __restrict__ wk,
                             const float* __restrict__ wv, const float* __restrict__ wo,
                             __half* __restrict__ dqkv, __half* __restrict__ dwo) {
    __shared__ float t[32][33];
    int z = blockIdx.z;
    int m = z >> 1, l = z & 1;
    const float* S = ((m == 0) ? wq : (m == 1) ? wk : (m == 2) ? wv : wo) + (long long)l * D_ * D_;
    __half* Dst = (m < 3) ? (dqkv + ((long long)l * 3 + m) * D_ * D_)
                          : (dwo + (long long)l * D_ * D_);
    int r0 = blockIdx.y * 32, c0 = blockIdx.x * 32;
    int c = c0 + threadIdx.x;
#pragma unroll
    for (int i = 0; i < 32; i += 8)
        t[threadIdx.y + i][threadIdx.x] = S[(long long)(r0 + threadIdx.y + i) * D_ + c];
    __syncthreads();
    int cc2 = r0 + threadIdx.x;
#pragma unroll
    for (int i = 0; i < 32; i += 8)
        Dst[(long long)(c0 + threadIdx.y + i) * D_ + cc2] = __float2half(t[threadIdx.x][threadIdx.y + i]);
}

// ---------------- warp-per-row layernorm (D=512, 16 halfs/lane) ----------------
template <bool RES>
__global__ void __launch_bounds__(256)
ln_k(const __half* __restrict__ X, const __half* __restrict__ Y,
     const float* __restrict__ g, const float* __restrict__ be,
     __half* __restrict__ out, int rows) {
    int row = blockIdx.x * 8 + (threadIdx.x >> 5);
    if (row >= rows) return;
    int lane = threadIdx.x & 31;
    int c0 = lane * 16;
    const __half* x = X + (long long)row * D_ + c0;

    float v[16];
    {
        uint4 xa = *(const uint4*)x;
        uint4 xb = *(const uint4*)(x + 8);
        const __half2* ph = (const __half2*)&xa;
#pragma unroll
        for (int i = 0; i < 4; i++) {
            float2 f = __half22float2(ph[i]);
            v[2 * i] = f.x; v[2 * i + 1] = f.y;
        }
        ph = (const __half2*)&xb;
#pragma unroll
        for (int i = 0; i < 4; i++) {
            float2 f = __half22float2(ph[i]);
            v[8 + 2 * i] = f.x; v[9 + 2 * i] = f.y;
        }
    }
    if (RES) {
        const __half* y = Y + (long long)row * D_ + c0;
        uint4 ya = *(const uint4*)y;
        uint4 yb = *(const uint4*)(y + 8);
        const __half2* ph = (const __half2*)&ya;
#pragma unroll
        for (int i = 0; i < 4; i++) {
            float2 f = __half22float2(ph[i]);
            v[2 * i] += f.x; v[2 * i + 1] += f.y;
        }
        ph = (const __half2*)&yb;
#pragma unroll
        for (int i = 0; i < 4; i++) {
            float2 f = __half22float2(ph[i]);
            v[8 + 2 * i] += f.x; v[9 + 2 * i] += f.y;
        }
    }

    float s = 0.f;
#pragma unroll
    for (int i = 0; i < 16; i++) s += v[i];
#pragma unroll
    for (int o = 16; o; o >>= 1) s += __shfl_xor_sync(0xffffffffu, s, o);
    float mean = s * (1.f / D_);
    float s2 = 0.f;
#pragma unroll
    for (int i = 0; i < 16; i++) { float d = v[i] - mean; s2 += d * d; }
#pragma unroll
    for (int o = 16; o; o >>= 1) s2 += __shfl_xor_sync(0xffffffffu, s2, o);
    float rstd = rsqrtf(s2 * (1.f / D_) + 1e-5f);

    uint32_t ov[8];
#pragma unroll
    for (int i = 0; i < 8; i++) {
        float g0 = g[c0 + 2 * i], g1 = g[c0 + 2 * i + 1];
        float b0 = be[c0 + 2 * i], b1 = be[c0 + 2 * i + 1];
        ov[i] = h2pack((v[2 * i] - mean) * rstd * g0 + b0,
                       (v[2 * i + 1] - mean) * rstd * g1 + b1);
    }
    __half* o = out + (long long)row * D_ + c0;
    *(uint4*)o = *(uint4*)&ov[0];
    *(uint4*)(o + 8) = *(uint4*)&ov[4];
}

// ---------------- small fused kernels ----------------
__global__ void revin_k(const float* __restrict__ x, const float* __restrict__ xm,
                        const float* __restrict__ gamma, const float* __restrict__ beta,
                        __half* __restrict__ tok,
                        float* __restrict__ meanO, float* __restrict__ stdO) {
    int idx = blockIdx.x * blockDim.x + threadIdx.x;
    if (idx < B_ * N_) {
        int b = idx / N_, n = idx % N_;
        const float* xp = x + (long long)b * L_ * N_ + n;
        float s = 0.f, s2 = 0.f;
#pragma unroll 4
        for (int l = 0; l < L_; l++) { float v = xp[(long long)l * N_]; s += v; s2 += v * v; }
        float mean = s / L_;
        float var = fmaxf(s2 / L_ - mean * mean, 0.f);
        float sd = sqrtf(var + 1e-5f);
        meanO[idx] = mean; stdO[idx] = sd;
        float g = gamma[n], be = beta[n], inv = 1.f / sd;
        __half* tp = tok + ((long long)b * T_ + n) * L_;
#pragma unroll 4
        for (int l = 0; l < L_; l++) tp[l] = __float2half((xp[(long long)l * N_] - mean) * inv * g + be);
    } else {
        int j = idx - B_ * N_;
        if (j < B_ * NMARK_ * L_) {
            int l = j % L_, m = (j / L_) % NMARK_, b = j / (L_ * NMARK_);
            tok[((long long)b * T_ + N_ + m) * L_ + l] = __float2half(xm[((long long)b * L_ + l) * NMARK_ + m]);
        }
    }
}

__global__ void trend_k(const __half* __restrict__ tok,
                        const float* __restrict__ w1, const float* __restrict__ b1,
                        const float* __restrict__ w2, const float* __restrict__ b2,
                        __half* __restrict__ nt) {
    int idx = blockIdx.x * blockDim.x + threadIdx.x;
    if (idx >= B_ * N_) return;
    int b = idx / N_, n = idx % N_;
    const __half* xp = tok + ((long long)b * T_ + n) * L_;
    float cum[L_ + 1];
    cum[0] = 0.f;
    float s = 0.f, s2 = 0.f;
    for (int l = 0; l < L_; l++) {
        float v = __half2float(xp[l]);
        cum[l + 1] = cum[l] + v;
        s += v; s2 += v * v;
    }
    float mean = s / L_;
    float var = fmaxf(s2 / L_ - mean * mean, 0.f);
    float sd = sqrtf(var + 1e-6f);
    float logits[4] = {b2[0], b2[1], b2[2], b2[3]};
#pragma unroll
    for (int j = 0; j < 16; j++) {
        float h = fmaxf(mean * w1[j] + sd * w1[16 + j] + b1[j], 0.f);
#pragma unroll
        for (int w = 0; w < 4; w++) logits[w] += h * w2[j * 4 + w];
    }
    float mx = fmaxf(fmaxf(logits[0], logits[1]), fmaxf(logits[2], logits[3]));
    float wt[4], ws = 0.f;
#pragma unroll
    for (int w = 0; w < 4; w++) { wt[w] = expf(logits[w] - mx); ws += wt[w]; }
#pragma unroll
    for (int w = 0; w < 4; w++) wt[w] /= ws;
    const int W[4] = {4, 8, 12, 24};
    float x0 = __half2float(xp[0]);
    float t[L_];
    float nrm2 = 0.f;
    for (int l = 0; l < L_; l++) {
        float tv = 0.f;
#pragma unroll
        for (int wi = 0; wi < 4; wi++) {
            int w = W[wi], lo = l - w + 1;
            float sum = (lo < 0) ? (cum[l + 1] + (float)(-lo) * x0) : (cum[l + 1] - cum[lo]);
            tv += wt[wi] * sum / (float)w;
        }
        t[l] = tv; nrm2 += tv * tv;
    }
    float inv = 1.f / fmaxf(sqrtf(nrm2), 1e-12f);
    __half* np = nt + ((long long)b * N_ + n) * L_;
    for (int l = 0; l < L_; l++) np[l] = __float2half(t[l] * inv);
}

__global__ void biascat_k(const float* __restrict__ bq, const float* __restrict__ bk,
                          const float* __restrict__ bv, float* __restrict__ o) {
    int i = blockIdx.x * blockDim.x + threadIdx.x;
    if (i >= LAYERS_ * 3 * D_) return;
    int l = i / (3 * D_), j = i % (3 * D_);
    float v = (j < D_) ? bq[l * D_ + j] : (j < 2 * D_) ? bk[l * D_ + j - D_] : bv[l * D_ + j - 2 * D_];
    o[i] = v;
}

__global__ void out_k(const float* __restrict__ proj, const float* __restrict__ meanI,
                      const float* __restrict__ stdI, const float* __restrict__ gamma,
                      const float* __restrict__ beta, float* __restrict__ out) {
    int idx = blockIdx.x * blockDim.x + threadIdx.x;
    if (idx >= B_ * PRED_ * N_) return;
    int n = idx % N_, p = (idx / N_) % PRED_, b = idx / (N_ * PRED_);
    float v = proj[((long long)b * T_ + n) * PRED_ + p];
    v = (v - beta[n]) / (gamma[n] + 1e-5f) * stdI[b * N_ + n] + meanI[b * N_ + n];
    out[idx] = v;
}

// ---------------- host orchestration ----------------
static inline dim3 tgrid(int M, int Nn, int batch) {
    return dim3((Nn + 127) / 128, (M + 127) / 128, batch);
}
#define SMEMB (2 * 2 * 128 * SSH * 2)

extern "C" void kernel_launch(void* const* d_in, const int* in_sizes, int n_in,
                              void* d_out, int out_size) {
    const float* x_enc  = (const float*)d_in[0];
    const float* x_mark = (const float*)d_in[1];
    const float* gamma  = (const float*)d_in[4];
    const float* beta   = (const float*)d_in[5];
    const float* tp_w1  = (const float*)d_in[6];
    const float* tp_b1  = (const float*)d_in[7];
    const float* tp_w2  = (const float*)d_in[8];
    const float* tp_b2  = (const float*)d_in[9];
    const float* emb_w  = (const float*)d_in[10];
    const float* emb_b  = (const float*)d_in[11];
    const float* wq = (const float*)d_in[12];
    const float* bq = (const float*)d_in[13];
    const float* wk = (const float*)d_in[14];
    const float* bk = (const float*)d_in[15];
    const float* wv = (const float*)d_in[16];
    const float* bv = (const float*)d_in[17];
    const float* wo = (const float*)d_in[18];
    const float* bo = (const float*)d_in[19];
    const float* w1 = (const float*)d_in[20];
    const float* b1 = (const float*)d_in[21];
    const float* w2 = (const float*)d_in[22];
    const float* b2 = (const float*)d_in[23];
    const float* ln1g = (const float*)d_in[24];
    const float* ln1b = (const float*)d_in[25];
    const float* ln2g = (const float*)d_in[26];
    const float* ln2b = (const float*)d_in[27];
    const float* normg = (const float*)d_in[28];
    const float* normb = (const float*)d_in[29];
    const float* proj_w = (const float*)d_in[30];
    const float* proj_b = (const float*)d_in[31];
    float* out = (float*)d_out;

    float *p_mean, *p_std, *p_guide, *p_bqkv, *p_proj;
    __half *p_tok, *p_nt, *p_x, *p_tmp, *p_ctx, *p_qkv, *p_ffn,
           *p_wqkvt, *p_wot, *p_w1t, *p_w2t, *p_embt, *p_projt;
    cudaGetSymbolAddress((void**)&p_mean, g_mean);
    cudaGetSymbolAddress((void**)&p_std, g_std);
    cudaGetSymbolAddress((void**)&p_guide, g_guide);
    cudaGetSymbolAddress((void**)&p_bqkv, g_bqkv);
    cudaGetSymbolAddress((void**)&p_proj, g_proj);
    cudaGetSymbolAddress((void**)&p_tok, g_tok);
    cudaGetSymbolAddress((void**)&p_nt, g_nt);
    cudaGetSymbolAddress((void**)&p_x, g_x);
    cudaGetSymbolAddress((void**)&p_tmp, g_tmp);
    cudaGetSymbolAddress((void**)&p_ctx, g_ctx);
    cudaGetSymbolAddress((void**)&p_qkv, g_qkv);
    cudaGetSymbolAddress((void**)&p_ffn, g_ffn);
    cudaGetSymbolAddress((void**)&p_wqkvt, g_wqkvt);
    cudaGetSymbolAddress((void**)&p_wot, g_wot);
    cudaGetSymbolAddress((void**)&p_w1t, g_w1t);
    cudaGetSymbolAddress((void**)&p_w2t, g_w2t);
    cudaGetSymbolAddress((void**)&p_embt, g_embt);
    cudaGetSymbolAddress((void**)&p_projt, g_projt);

    cudaFuncSetAttribute(mmak<4, float>,  cudaFuncAttributeMaxDynamicSharedMemorySize, SMEMB);
    cudaFuncSetAttribute(mmak<1, __half>, cudaFuncAttributeMaxDynamicSharedMemorySize, SMEMB);
    cudaFuncSetAttribute(mmak<1, float>,  cudaFuncAttributeMaxDynamicSharedMemorySize, SMEMB);
    cudaFuncSetAttribute(mmak<2, __half>, cudaFuncAttributeMaxDynamicSharedMemorySize, SMEMB);
    cudaFuncSetAttribute(mmak<3, __half>, cudaFuncAttributeMaxDynamicSharedMemorySize, SMEMB);
    cudaFuncSetAttribute(flash_k, cudaFuncAttributeMaxDynamicSharedMemorySize, FSMEM);

    dim3 tb(32, 8);
    const int LNG = (BT_ + 7) / 8;

    revin_k<<<(B_ * N_ + B_ * NMARK_ * L_ + 255) / 256, 256>>>(
        x_enc, x_mark, gamma, beta, p_tok, p_mean, p_std);
    trend_k<<<(B_ * N_ + 255) / 256, 256>>>(p_tok, tp_w1, tp_b1, tp_w2, tp_b2, p_nt);
    transpose_k<<<dim3(16, 3, 1), tb>>>(emb_w, p_embt, L_, D_, D_, L_, 1, 0, 0, 0, 0);

    // Gram with fused sigmoid -> gate
    mmak<4, float><<<tgrid(N_, N_, B_), 256, SMEMB>>>(
        p_nt, p_nt, nullptr, nullptr, p_guide, N_, N_, L_, L_, L_, N_, 1,
        (long long)N_ * L_, 0, (long long)N_ * L_, 0, (long long)N_ * N_, 0);
    // embedding
    mmak<1, __half><<<tgrid(BT_, D_, 1), 256, SMEMB>>>(
        p_tok, p_embt, emb_b, nullptr, p_x, BT_, D_, L_, L_, L_, D_, 1, 0, 0, 0, 0, 0, 0);

    transpose4_k<<<dim3(16, 16, 8), tb>>>(wq, wk, wv, wo, p_wqkvt, p_wot);
    biascat_k<<<(LAYERS_ * 3 * D_ + 255) / 256, 256>>>(bq, bk, bv, p_bqkv);
    transpose_k<<<dim3(64, 16, 2), tb>>>(w1, p_w1t, 512, 2048, 2048, 512, 1,
                                         (long long)512 * 2048, 0, (long long)512 * 2048, 0);
    transpose_k<<<dim3(16, 64, 2), tb>>>(w2, p_w2t, 2048, 512, 512, 2048, 1,
                                         (long long)512 * 2048, 0, (long long)512 * 2048, 0);
    transpose_k<<<dim3(3, 16, 1), tb>>>(proj_w, p_projt, D_, PRED_, PRED_, D_, 1, 0, 0, 0, 0);

    for (int i = 0; i < LAYERS_; i++) {
        const __half* wqkvt_i = p_wqkvt + (long long)i * 3 * D_ * D_;
        const __half* wot_i = p_wot + (long long)i * D_ * D_;
        const __half* w1t_i = p_w1t + (long long)i * D_ * DFF_;
        const __half* w2t_i = p_w2t + (long long)i * DFF_ * D_;

        mmak<1, __half><<<tgrid(BT_, 3 * D_, 1), 256, SMEMB>>>(
            p_x, wqkvt_i, p_bqkv + i * 3 * D_, nullptr, p_qkv,
            BT_, 3 * D_, D_, D_, D_, 3 * D_, 1, 0, 0, 0, 0, 0, 0);

        flash_k<<<dim3(5, B_ * H_), 256, FSMEM>>>(p_qkv, p_guide, p_ctx);

        mmak<3, __half><<<tgrid(BT_, D_, 1), 256, SMEMB>>>(
            p_ctx, wot_i, bo + i * D_, p_x, p_tmp, BT_, D_, D_, D_, D_, D_, 1, 0, 0, 0, 0, 0, 0);

        ln_k<false><<<LNG, 256>>>(p_tmp, nullptr, ln1g + i * D_, ln1b + i * D_, p_tmp, BT_);

        mmak<2, __half><<<tgrid(BT_, DFF_, 1), 256, SMEMB>>>(
            p_tmp, w1t_i, b1 + i * DFF_, nullptr, p_ffn, BT_, DFF_, D_, D_, D_, DFF_, 1, 0, 0, 0, 0, 0, 0);
        mmak<1, __half><<<tgrid(BT_, D_, 1), 256, SMEMB>>>(
            p_ffn, w2t_i, b2 + i * D_, nullptr, p_ctx, BT_, D_, DFF_, DFF_, DFF_, D_, 1, 0, 0, 0, 0, 0, 0);

        ln_k<true><<<LNG, 256>>>(p_tmp, p_ctx, ln2g + i * D_, ln2b + i * D_, p_x, BT_);
    }

    ln_k<false><<<LNG, 256>>>(p_x, nullptr, normg, normb, p_tmp, BT_);

    mmak<1, float><<<tgrid(BT_, PRED_, 1), 256, SMEMB>>>(
        p_tmp, p_projt, proj_b, nullptr, p_proj, BT_, PRED_, D_, D_, D_, PRED_, 1, 0, 0, 0, 0, 0, 0);

    out_k<<<(B_ * PRED_ * N_ + 255) / 256, 256>>>(p_proj, p_mean, p_std, gamma, beta, out);
}